// round 14
// baseline (speedup 1.0000x reference)
#include <cuda_runtime.h>
#include <cuda_fp16.h>
#include <cstdint>

// Problem constants
#define NTRI 32
#define TSTEPS 512
#define IDIM 64
#define NN 4096
#define RR 8
#define ODIM 64
#define DT 0.1f

#define XSEQ_ELEMS (32ll * 513 * 4096)

// Scratch: inp_proj [b][t][j] : 32*512*4096 floats = 268 MB
__device__ float g_uproj[(size_t)NTRI * TSTEPS * NN];

__device__ __forceinline__ float sigmoid_fast(float x) {
    float t;
    asm("tanh.approx.f32 %0, %1;" : "=f"(t) : "f"(0.5f * x));
    return fmaf(0.5f, t, 0.5f);
}

__device__ __forceinline__ __half2 shfl_xor_h2(__half2 v, int m) {
    unsigned u = *reinterpret_cast<unsigned*>(&v);
    u = __shfl_xor_sync(0xffffffffu, u, m);
    return *reinterpret_cast<__half2*>(&u);
}

__device__ __forceinline__ unsigned h2bits(__half2 v) {
    return *reinterpret_cast<unsigned*>(&v);
}

// ---- packed f32x2 (Blackwell FFMA2) ----
__device__ __forceinline__ unsigned long long pack2(float lo, float hi) {
    unsigned long long r;
    asm("mov.b64 %0, {%1, %2};" : "=l"(r) : "f"(lo), "f"(hi));
    return r;
}
__device__ __forceinline__ void unpack2(unsigned long long v, float& lo, float& hi) {
    asm("mov.b64 {%0, %1}, %2;" : "=f"(lo), "=f"(hi) : "l"(v));
}
__device__ __forceinline__ unsigned long long ffma2(unsigned long long a,
                                                    unsigned long long b,
                                                    unsigned long long c) {
    unsigned long long d;
    asm("fma.rn.f32x2 %0, %1, %2, %3;" : "=l"(d) : "l"(a), "l"(b), "l"(c));
    return d;
}

// ---------------------------------------------------------------------------
// Kernel 1: inp_proj[b][t][j] = sum_i inp[b][t][i] * B[j][i]  (R9 config)
// ---------------------------------------------------------------------------
__global__ void __launch_bounds__(256) proj_kernel(const float* __restrict__ inp,
                                                   const float* __restrict__ B) {
    __shared__ __align__(16) float a_s[32][132];
    __shared__ __align__(16) float b_s[32][68];

    const int tid = threadIdx.x;
    const int g0 = blockIdx.y * 128;
    const int jb0 = blockIdx.x * 64;
    const int ty = tid >> 4;
    const int tx = tid & 15;
    const int bt0 = ty * 8;
    const int j0 = tx * 4;

    unsigned long long acc2[4][4];
#pragma unroll
    for (int i = 0; i < 4; i++)
#pragma unroll
        for (int j = 0; j < 4; j++) acc2[i][j] = 0ull;

#pragma unroll
    for (int kc = 0; kc < 2; kc++) {
        if (kc) __syncthreads();
#pragma unroll
        for (int it = 0; it < 4; it++) {
            int q = tid + it * 256;
            int r = q >> 3;
            int c4 = q & 7;
            float4 av = *(const float4*)(inp + (size_t)(g0 + r) * 64 + kc * 32 + c4 * 4);
            a_s[c4 * 4 + 0][r] = av.x;
            a_s[c4 * 4 + 1][r] = av.y;
            a_s[c4 * 4 + 2][r] = av.z;
            a_s[c4 * 4 + 3][r] = av.w;
        }
#pragma unroll
        for (int it = 0; it < 2; it++) {
            int q = tid + it * 256;
            int jr = q >> 3;
            int c4 = q & 7;
            float4 bv = *(const float4*)(B + (size_t)(jb0 + jr) * 64 + kc * 32 + c4 * 4);
            b_s[c4 * 4 + 0][jr] = bv.x;
            b_s[c4 * 4 + 1][jr] = bv.y;
            b_s[c4 * 4 + 2][jr] = bv.z;
            b_s[c4 * 4 + 3][jr] = bv.w;
        }
        __syncthreads();
#pragma unroll
        for (int k = 0; k < 32; k++) {
            ulonglong2 ap0 = *(const ulonglong2*)&a_s[k][bt0];
            ulonglong2 ap1 = *(const ulonglong2*)&a_s[k][bt0 + 4];
            unsigned long long ap[4] = {ap0.x, ap0.y, ap1.x, ap1.y};
            float4 bb = *(const float4*)&b_s[k][j0];
            unsigned long long bd[4] = {pack2(bb.x, bb.x), pack2(bb.y, bb.y),
                                        pack2(bb.z, bb.z), pack2(bb.w, bb.w)};
#pragma unroll
            for (int i = 0; i < 4; i++)
#pragma unroll
                for (int j = 0; j < 4; j++) acc2[i][j] = ffma2(ap[i], bd[j], acc2[i][j]);
        }
    }
#pragma unroll
    for (int i = 0; i < 4; i++) {
        float r0[4], r1[4];
#pragma unroll
        for (int j = 0; j < 4; j++) unpack2(acc2[i][j], r0[j], r1[j]);
        *(float4*)(g_uproj + (size_t)(g0 + bt0 + 2 * i) * NN + jb0 + j0) =
            make_float4(r0[0], r0[1], r0[2], r0[3]);
        *(float4*)(g_uproj + (size_t)(g0 + bt0 + 2 * i + 1) * NN + jb0 + j0) =
            make_float4(r1[0], r1[1], r1[2], r1[3]);
    }
}

// ---------------------------------------------------------------------------
// Kernel 2: recurrence (R9 config, proven 1024us / 4.9e-6).
// ---------------------------------------------------------------------------
__global__ void __launch_bounds__(512, 1) rnn_scan_kernel(const float* __restrict__ mg,
                                                          const float* __restrict__ ng,
                                                          float* __restrict__ xseq) {
    const int b = blockIdx.x;
    const int tid = threadIdx.x;
    const int j0 = tid * 8;
    const unsigned lane = tid & 31;
    const unsigned warp = tid >> 5;

    __shared__ __half2 part[2][4][16];

    __half2 nP[8][4];
    __half2 mPP[4][8];
#pragma unroll
    for (int k = 0; k < 8; k++) {
        const float* nr = ng + (size_t)(j0 + k) * RR;
#pragma unroll
        for (int p = 0; p < 4; p++) nP[k][p] = __floats2half2_rn(nr[2 * p], nr[2 * p + 1]);
    }
#pragma unroll
    for (int p = 0; p < 4; p++) {
        const float* m0 = mg + (size_t)(j0 + 2 * p) * RR;
        const float* m1 = mg + (size_t)(j0 + 2 * p + 1) * RR;
#pragma unroll
        for (int r = 0; r < 8; r++) mPP[p][r] = __floats2half2_rn(m0[r] * DT, m1[r] * DT);
    }

    float x[8];
    __half2 sd[8];
    const __half2 half05 = __floats2half2_rn(0.5f, 0.5f);
#pragma unroll
    for (int k = 0; k < 8; k++) {
        x[k] = 0.f;
        sd[k] = half05;
    }

    float* xrow0 = xseq + (size_t)b * 513 * NN;
    const float4 z4 = make_float4(0.f, 0.f, 0.f, 0.f);
    *(float4*)(xrow0 + j0) = z4;
    *(float4*)(xrow0 + j0 + 4) = z4;

    const float* up = g_uproj + (size_t)b * TSTEPS * NN + j0;
    const float keep = 1.0f - DT;
    const __half2 invN2 = __floats2half2_rn(1.0f / (float)NN, 1.0f / (float)NN);
    const bool hi16 = (lane & 16) != 0;
    const bool hi8 = (lane & 8) != 0;
    const bool lo16 = !hi16;

    float4 u0 = __ldg((const float4*)up);
    float4 u1 = __ldg((const float4*)(up + 4));

    for (int t = 0; t < TSTEPS; t++) {
        float4 p0, p1;
        if (t + 1 < TSTEPS) {
            p0 = __ldg((const float4*)(up + (size_t)(t + 1) * NN));
            p1 = __ldg((const float4*)(up + (size_t)(t + 1) * NN + 4));
        } else {
            p0 = z4; p1 = z4;
        }

        __half2 h[4];
#pragma unroll
        for (int p = 0; p < 4; p++) h[p] = __floats2half2_rn(0.f, 0.f);
#pragma unroll
        for (int k = 0; k < 8; k++) {
#pragma unroll
            for (int p = 0; p < 4; p++) h[p] = __hfma2(sd[k], nP[k][p], h[p]);
        }

#pragma unroll
        for (int p = 0; p < 2; p++) {
            __half2 snd = hi16 ? h[p] : h[p + 2];
            __half2 rcv = shfl_xor_h2(snd, 16);
            h[p] = __hadd2(hi16 ? h[p + 2] : h[p], rcv);
        }
        {
            __half2 snd = hi8 ? h[0] : h[1];
            __half2 rcv = shfl_xor_h2(snd, 8);
            h[0] = __hadd2(hi8 ? h[1] : h[0], rcv);
        }
        h[0] = __hadd2(h[0], shfl_xor_h2(h[0], 4));
        h[0] = __hadd2(h[0], shfl_xor_h2(h[0], 2));
        h[0] = __hadd2(h[0], shfl_xor_h2(h[0], 1));

        const int buf = t & 1;
        if ((lane & 7) == 0) {
            part[buf][lane >> 3][warp] = h[0];
        }
        __syncthreads();

        const __half2* flat = &part[buf][0][0];
        __half2 a = flat[lane];
        __half2 c = flat[lane + 32];
#pragma unroll
        for (int d = 8; d > 0; d >>= 1) {
            a = __hadd2(a, shfl_xor_h2(a, d));
            c = __hadd2(c, shfl_xor_h2(c, d));
        }
        __half2 a2 = shfl_xor_h2(a, 16);
        __half2 c2 = shfl_xor_h2(c, 16);
        __half2 vh[4];
        vh[0] = __hmul2(lo16 ? a : a2, invN2);
        vh[1] = __hmul2(lo16 ? a2 : a, invN2);
        vh[2] = __hmul2(lo16 ? c : c2, invN2);
        vh[3] = __hmul2(lo16 ? c2 : c, invN2);

        __half2 vb[8];
#pragma unroll
        for (int p = 0; p < 4; p++) {
            vb[2 * p] = __low2half2(vh[p]);
            vb[2 * p + 1] = __high2half2(vh[p]);
        }

        float ua[8] = {u0.x, u0.y, u0.z, u0.w, u1.x, u1.y, u1.z, u1.w};

#pragma unroll
        for (int p = 0; p < 4; p++) {
            __half2 rp = __hmul2(vb[0], mPP[p][0]);
#pragma unroll
            for (int r = 1; r < 8; r++) rp = __hfma2(vb[r], mPP[p][r], rp);
            float2 rf = __half22float2(rp);
            const int k0 = 2 * p, k1 = 2 * p + 1;
            x[k0] = fmaf(keep, x[k0], fmaf(DT, ua[k0], rf.x));
            x[k1] = fmaf(keep, x[k1], fmaf(DT, ua[k1], rf.y));
            float s0 = sigmoid_fast(x[k0]);
            float s1 = sigmoid_fast(x[k1]);
            sd[k0] = __half2half2(__float2half_rn(s0));
            sd[k1] = __half2half2(__float2half_rn(s1));
        }

        float* dst = xrow0 + (size_t)(t + 1) * NN + j0;
        *(float4*)dst = make_float4(x[0], x[1], x[2], x[3]);
        *(float4*)(dst + 4) = make_float4(x[4], x[5], x[6], x[7]);

        u0 = p0; u1 = p1;
    }
}

// ---------------------------------------------------------------------------
// Kernel 3: y[b][t][o] = sum_j sigmoid(x_seq[b][t+1][j]) * W[o][j]
// Tensor-core version: mma.sync.m16n8k16 fp16 inputs, fp32 accum.
// CTA: 128 thr (4 warps), tile 64bt x 64o, K chunks of 64.
// ---------------------------------------------------------------------------
__global__ void __launch_bounds__(128) out_kernel(const float* __restrict__ xseq,
                                                  const float* __restrict__ W,
                                                  float* __restrict__ out2) {
    __shared__ __align__(16) __half xh[64][72];  // [bt][k] sigmoid applied
    __shared__ __align__(16) __half wh[64][72];  // [o][k]

    const int tid = threadIdx.x;
    const int warp = tid >> 5;
    const int lane = tid & 31;
    const int g0 = blockIdx.x * 64;  // bt base (64 | 512: within one trial)
    const int bb = g0 >> 9;
    const int t0 = g0 & 511;
    const float* xbase = xseq + (size_t)bb * 513 * NN + (size_t)(t0 + 1) * NN;

    float acc[8][4];
#pragma unroll
    for (int ot = 0; ot < 8; ot++)
#pragma unroll
        for (int i = 0; i < 4; i++) acc[ot][i] = 0.f;

    for (int kc = 0; kc < NN; kc += 64) {
        if (kc) __syncthreads();
        // load x tile (sigmoid+cvt) and W tile (cvt): 64 rows x 64 k each
#pragma unroll
        for (int it = 0; it < 8; it++) {
            int idx = tid + it * 128;   // 0..1023
            int r = idx >> 4;           // row 0..63
            int c = (idx & 15) * 4;     // k col
            float4 xv = *(const float4*)(xbase + (size_t)r * NN + kc + c);
            __half2 h0 = __floats2half2_rn(sigmoid_fast(xv.x), sigmoid_fast(xv.y));
            __half2 h1 = __floats2half2_rn(sigmoid_fast(xv.z), sigmoid_fast(xv.w));
            *(uint2*)&xh[r][c] = make_uint2(h2bits(h0), h2bits(h1));
            float4 wv = *(const float4*)(W + (size_t)r * NN + kc + c);
            __half2 w0 = __floats2half2_rn(wv.x, wv.y);
            __half2 w1 = __floats2half2_rn(wv.z, wv.w);
            *(uint2*)&wh[r][c] = make_uint2(h2bits(w0), h2bits(w1));
        }
        __syncthreads();

#pragma unroll
        for (int k0 = 0; k0 < 64; k0 += 16) {
            // A fragment: 16x16 tile at rows [warp*16, +16), cols [k0, +16)
            unsigned a0, a1, a2, a3;
            {
                unsigned addr = (unsigned)__cvta_generic_to_shared(
                    &xh[warp * 16 + (lane & 15)][k0 + ((lane >> 4) << 3)]);
                asm volatile(
                    "ldmatrix.sync.aligned.m8n8.x4.shared.b16 {%0,%1,%2,%3}, [%4];"
                    : "=r"(a0), "=r"(a1), "=r"(a2), "=r"(a3) : "r"(addr));
            }
#pragma unroll
            for (int ot = 0; ot < 8; ot++) {
                unsigned b0, b1;
                unsigned baddr = (unsigned)__cvta_generic_to_shared(
                    &wh[ot * 8 + (lane & 7)][k0 + ((lane >> 3) & 1) * 8]);
                asm volatile(
                    "ldmatrix.sync.aligned.m8n8.x2.shared.b16 {%0,%1}, [%2];"
                    : "=r"(b0), "=r"(b1) : "r"(baddr));
                asm volatile(
                    "mma.sync.aligned.m16n8k16.row.col.f32.f16.f16.f32 "
                    "{%0,%1,%2,%3}, {%4,%5,%6,%7}, {%8,%9}, {%0,%1,%2,%3};"
                    : "+f"(acc[ot][0]), "+f"(acc[ot][1]), "+f"(acc[ot][2]), "+f"(acc[ot][3])
                    : "r"(a0), "r"(a1), "r"(a2), "r"(a3), "r"(b0), "r"(b1));
            }
        }
    }

    // epilogue: thread holds (c0,c1)@row=lane/4, (c2,c3)@row+8; cols = (lane%4)*2
    const int gid = lane >> 2;
    const int qid = lane & 3;
    const int m0 = g0 + warp * 16 + gid;
#pragma unroll
    for (int ot = 0; ot < 8; ot++) {
        int o = ot * 8 + qid * 2;
        *(float2*)(out2 + (size_t)m0 * ODIM + o) = make_float2(acc[ot][0], acc[ot][1]);
        *(float2*)(out2 + (size_t)(m0 + 8) * ODIM + o) = make_float2(acc[ot][2], acc[ot][3]);
    }
}

// ---------------------------------------------------------------------------
extern "C" void kernel_launch(void* const* d_in, const int* in_sizes, int n_in,
                              void* d_out, int out_size) {
    const float* inp = (const float*)d_in[0];  // [32,512,64]
    const float* B = (const float*)d_in[1];    // [4096,64]
    const float* W = (const float*)d_in[2];    // [64,4096]
    const float* m = (const float*)d_in[3];    // [4096,8]
    const float* n = (const float*)d_in[4];    // [4096,8]

    float* xseq = (float*)d_out;               // [32,513,4096]
    float* out2 = (float*)d_out + XSEQ_ELEMS;  // [32,512,64]

    {
        dim3 grid(NN / 64, (NTRI * TSTEPS) / 128);
        proj_kernel<<<grid, 256>>>(inp, B);
    }
    rnn_scan_kernel<<<NTRI, 512>>>(m, n, xseq);
    out_kernel<<<(NTRI * TSTEPS) / 64, 128>>>(xseq, W, out2);
}

// round 15
// speedup vs baseline: 1.0143x; 1.0143x over previous
#include <cuda_runtime.h>
#include <cuda_fp16.h>
#include <cstdint>

// Problem constants
#define NTRI 32
#define TSTEPS 512
#define IDIM 64
#define NN 4096
#define RR 8
#define ODIM 64
#define DT 0.1f

#define XSEQ_ELEMS (32ll * 513 * 4096)

// Scratch: inp_proj [b][t][j] : 32*512*4096 floats = 268 MB
__device__ float g_uproj[(size_t)NTRI * TSTEPS * NN];

__device__ __forceinline__ float sigmoid_fast(float x) {
    float t;
    asm("tanh.approx.f32 %0, %1;" : "=f"(t) : "f"(0.5f * x));
    return fmaf(0.5f, t, 0.5f);
}

__device__ __forceinline__ __half2 shfl_xor_h2(__half2 v, int m) {
    unsigned u = *reinterpret_cast<unsigned*>(&v);
    u = __shfl_xor_sync(0xffffffffu, u, m);
    return *reinterpret_cast<__half2*>(&u);
}

__device__ __forceinline__ unsigned h2bits(__half2 v) {
    return *reinterpret_cast<unsigned*>(&v);
}

// ---- packed f32x2 (Blackwell FFMA2) ----
__device__ __forceinline__ unsigned long long pack2(float lo, float hi) {
    unsigned long long r;
    asm("mov.b64 %0, {%1, %2};" : "=l"(r) : "f"(lo), "f"(hi));
    return r;
}
__device__ __forceinline__ void unpack2(unsigned long long v, float& lo, float& hi) {
    asm("mov.b64 {%0, %1}, %2;" : "=f"(lo), "=f"(hi) : "l"(v));
}
__device__ __forceinline__ unsigned long long ffma2(unsigned long long a,
                                                    unsigned long long b,
                                                    unsigned long long c) {
    unsigned long long d;
    asm("fma.rn.f32x2 %0, %1, %2, %3;" : "=l"(d) : "l"(a), "l"(b), "l"(c));
    return d;
}

// ---------------------------------------------------------------------------
// Kernel 1: inp_proj[b][t][j] = sum_i inp[b][t][i] * B[j][i]  (R9 config)
// ---------------------------------------------------------------------------
__global__ void __launch_bounds__(256) proj_kernel(const float* __restrict__ inp,
                                                   const float* __restrict__ B) {
    __shared__ __align__(16) float a_s[32][132];
    __shared__ __align__(16) float b_s[32][68];

    const int tid = threadIdx.x;
    const int g0 = blockIdx.y * 128;
    const int jb0 = blockIdx.x * 64;
    const int ty = tid >> 4;
    const int tx = tid & 15;
    const int bt0 = ty * 8;
    const int j0 = tx * 4;

    unsigned long long acc2[4][4];
#pragma unroll
    for (int i = 0; i < 4; i++)
#pragma unroll
        for (int j = 0; j < 4; j++) acc2[i][j] = 0ull;

#pragma unroll
    for (int kc = 0; kc < 2; kc++) {
        if (kc) __syncthreads();
#pragma unroll
        for (int it = 0; it < 4; it++) {
            int q = tid + it * 256;
            int r = q >> 3;
            int c4 = q & 7;
            float4 av = *(const float4*)(inp + (size_t)(g0 + r) * 64 + kc * 32 + c4 * 4);
            a_s[c4 * 4 + 0][r] = av.x;
            a_s[c4 * 4 + 1][r] = av.y;
            a_s[c4 * 4 + 2][r] = av.z;
            a_s[c4 * 4 + 3][r] = av.w;
        }
#pragma unroll
        for (int it = 0; it < 2; it++) {
            int q = tid + it * 256;
            int jr = q >> 3;
            int c4 = q & 7;
            float4 bv = *(const float4*)(B + (size_t)(jb0 + jr) * 64 + kc * 32 + c4 * 4);
            b_s[c4 * 4 + 0][jr] = bv.x;
            b_s[c4 * 4 + 1][jr] = bv.y;
            b_s[c4 * 4 + 2][jr] = bv.z;
            b_s[c4 * 4 + 3][jr] = bv.w;
        }
        __syncthreads();
#pragma unroll
        for (int k = 0; k < 32; k++) {
            ulonglong2 ap0 = *(const ulonglong2*)&a_s[k][bt0];
            ulonglong2 ap1 = *(const ulonglong2*)&a_s[k][bt0 + 4];
            unsigned long long ap[4] = {ap0.x, ap0.y, ap1.x, ap1.y};
            float4 bb = *(const float4*)&b_s[k][j0];
            unsigned long long bd[4] = {pack2(bb.x, bb.x), pack2(bb.y, bb.y),
                                        pack2(bb.z, bb.z), pack2(bb.w, bb.w)};
#pragma unroll
            for (int i = 0; i < 4; i++)
#pragma unroll
                for (int j = 0; j < 4; j++) acc2[i][j] = ffma2(ap[i], bd[j], acc2[i][j]);
        }
    }
#pragma unroll
    for (int i = 0; i < 4; i++) {
        float r0[4], r1[4];
#pragma unroll
        for (int j = 0; j < 4; j++) unpack2(acc2[i][j], r0[j], r1[j]);
        *(float4*)(g_uproj + (size_t)(g0 + bt0 + 2 * i) * NN + jb0 + j0) =
            make_float4(r0[0], r0[1], r0[2], r0[3]);
        *(float4*)(g_uproj + (size_t)(g0 + bt0 + 2 * i + 1) * NN + jb0 + j0) =
            make_float4(r1[0], r1[1], r1[2], r1[3]);
    }
}

// ---------------------------------------------------------------------------
// Kernel 2: recurrence (R9 config, proven 1024us / 4.9e-6).
// ---------------------------------------------------------------------------
__global__ void __launch_bounds__(512, 1) rnn_scan_kernel(const float* __restrict__ mg,
                                                          const float* __restrict__ ng,
                                                          float* __restrict__ xseq) {
    const int b = blockIdx.x;
    const int tid = threadIdx.x;
    const int j0 = tid * 8;
    const unsigned lane = tid & 31;
    const unsigned warp = tid >> 5;

    __shared__ __half2 part[2][4][16];

    __half2 nP[8][4];
    __half2 mPP[4][8];
#pragma unroll
    for (int k = 0; k < 8; k++) {
        const float* nr = ng + (size_t)(j0 + k) * RR;
#pragma unroll
        for (int p = 0; p < 4; p++) nP[k][p] = __floats2half2_rn(nr[2 * p], nr[2 * p + 1]);
    }
#pragma unroll
    for (int p = 0; p < 4; p++) {
        const float* m0 = mg + (size_t)(j0 + 2 * p) * RR;
        const float* m1 = mg + (size_t)(j0 + 2 * p + 1) * RR;
#pragma unroll
        for (int r = 0; r < 8; r++) mPP[p][r] = __floats2half2_rn(m0[r] * DT, m1[r] * DT);
    }

    float x[8];
    __half2 sd[8];
    const __half2 half05 = __floats2half2_rn(0.5f, 0.5f);
#pragma unroll
    for (int k = 0; k < 8; k++) {
        x[k] = 0.f;
        sd[k] = half05;
    }

    float* xrow0 = xseq + (size_t)b * 513 * NN;
    const float4 z4 = make_float4(0.f, 0.f, 0.f, 0.f);
    *(float4*)(xrow0 + j0) = z4;
    *(float4*)(xrow0 + j0 + 4) = z4;

    const float* up = g_uproj + (size_t)b * TSTEPS * NN + j0;
    const float keep = 1.0f - DT;
    const __half2 invN2 = __floats2half2_rn(1.0f / (float)NN, 1.0f / (float)NN);
    const bool hi16 = (lane & 16) != 0;
    const bool hi8 = (lane & 8) != 0;
    const bool lo16 = !hi16;

    float4 u0 = __ldg((const float4*)up);
    float4 u1 = __ldg((const float4*)(up + 4));

    for (int t = 0; t < TSTEPS; t++) {
        float4 p0, p1;
        if (t + 1 < TSTEPS) {
            p0 = __ldg((const float4*)(up + (size_t)(t + 1) * NN));
            p1 = __ldg((const float4*)(up + (size_t)(t + 1) * NN + 4));
        } else {
            p0 = z4; p1 = z4;
        }

        __half2 h[4];
#pragma unroll
        for (int p = 0; p < 4; p++) h[p] = __floats2half2_rn(0.f, 0.f);
#pragma unroll
        for (int k = 0; k < 8; k++) {
#pragma unroll
            for (int p = 0; p < 4; p++) h[p] = __hfma2(sd[k], nP[k][p], h[p]);
        }

#pragma unroll
        for (int p = 0; p < 2; p++) {
            __half2 snd = hi16 ? h[p] : h[p + 2];
            __half2 rcv = shfl_xor_h2(snd, 16);
            h[p] = __hadd2(hi16 ? h[p + 2] : h[p], rcv);
        }
        {
            __half2 snd = hi8 ? h[0] : h[1];
            __half2 rcv = shfl_xor_h2(snd, 8);
            h[0] = __hadd2(hi8 ? h[1] : h[0], rcv);
        }
        h[0] = __hadd2(h[0], shfl_xor_h2(h[0], 4));
        h[0] = __hadd2(h[0], shfl_xor_h2(h[0], 2));
        h[0] = __hadd2(h[0], shfl_xor_h2(h[0], 1));

        const int buf = t & 1;
        if ((lane & 7) == 0) {
            part[buf][lane >> 3][warp] = h[0];
        }
        __syncthreads();

        const __half2* flat = &part[buf][0][0];
        __half2 a = flat[lane];
        __half2 c = flat[lane + 32];
#pragma unroll
        for (int d = 8; d > 0; d >>= 1) {
            a = __hadd2(a, shfl_xor_h2(a, d));
            c = __hadd2(c, shfl_xor_h2(c, d));
        }
        __half2 a2 = shfl_xor_h2(a, 16);
        __half2 c2 = shfl_xor_h2(c, 16);
        __half2 vh[4];
        vh[0] = __hmul2(lo16 ? a : a2, invN2);
        vh[1] = __hmul2(lo16 ? a2 : a, invN2);
        vh[2] = __hmul2(lo16 ? c : c2, invN2);
        vh[3] = __hmul2(lo16 ? c2 : c, invN2);

        __half2 vb[8];
#pragma unroll
        for (int p = 0; p < 4; p++) {
            vb[2 * p] = __low2half2(vh[p]);
            vb[2 * p + 1] = __high2half2(vh[p]);
        }

        float ua[8] = {u0.x, u0.y, u0.z, u0.w, u1.x, u1.y, u1.z, u1.w};

#pragma unroll
        for (int p = 0; p < 4; p++) {
            __half2 rp = __hmul2(vb[0], mPP[p][0]);
#pragma unroll
            for (int r = 1; r < 8; r++) rp = __hfma2(vb[r], mPP[p][r], rp);
            float2 rf = __half22float2(rp);
            const int k0 = 2 * p, k1 = 2 * p + 1;
            x[k0] = fmaf(keep, x[k0], fmaf(DT, ua[k0], rf.x));
            x[k1] = fmaf(keep, x[k1], fmaf(DT, ua[k1], rf.y));
            float s0 = sigmoid_fast(x[k0]);
            float s1 = sigmoid_fast(x[k1]);
            sd[k0] = __half2half2(__float2half_rn(s0));
            sd[k1] = __half2half2(__float2half_rn(s1));
        }

        float* dst = xrow0 + (size_t)(t + 1) * NN + j0;
        *(float4*)dst = make_float4(x[0], x[1], x[2], x[3]);
        *(float4*)(dst + 4) = make_float4(x[4], x[5], x[6], x[7]);

        u0 = p0; u1 = p1;
    }
}

// ---------------------------------------------------------------------------
// Kernel 3: y[b][t][o] = sum_j sigmoid(x_seq[b][t+1][j]) * W[o][j]
// Tensor-core version: mma.sync.m16n8k16 fp16 inputs, fp32 accum.
// CTA: 128 thr (4 warps), tile 64bt x 64o, K chunks of 64.
// ---------------------------------------------------------------------------
__global__ void __launch_bounds__(128) out_kernel(const float* __restrict__ xseq,
                                                  const float* __restrict__ W,
                                                  float* __restrict__ out2) {
    __shared__ __align__(16) __half xh[64][72];  // [bt][k] sigmoid applied
    __shared__ __align__(16) __half wh[64][72];  // [o][k]

    const int tid = threadIdx.x;
    const int warp = tid >> 5;
    const int lane = tid & 31;
    const int g0 = blockIdx.x * 64;  // bt base (64 | 512: within one trial)
    const int bb = g0 >> 9;
    const int t0 = g0 & 511;
    const float* xbase = xseq + (size_t)bb * 513 * NN + (size_t)(t0 + 1) * NN;

    float acc[8][4];
#pragma unroll
    for (int ot = 0; ot < 8; ot++)
#pragma unroll
        for (int i = 0; i < 4; i++) acc[ot][i] = 0.f;

    for (int kc = 0; kc < NN; kc += 64) {
        if (kc) __syncthreads();
        // load x tile (sigmoid+cvt) and W tile (cvt): 64 rows x 64 k each
#pragma unroll
        for (int it = 0; it < 8; it++) {
            int idx = tid + it * 128;   // 0..1023
            int r = idx >> 4;           // row 0..63
            int c = (idx & 15) * 4;     // k col
            float4 xv = *(const float4*)(xbase + (size_t)r * NN + kc + c);
            __half2 h0 = __floats2half2_rn(sigmoid_fast(xv.x), sigmoid_fast(xv.y));
            __half2 h1 = __floats2half2_rn(sigmoid_fast(xv.z), sigmoid_fast(xv.w));
            *(uint2*)&xh[r][c] = make_uint2(h2bits(h0), h2bits(h1));
            float4 wv = *(const float4*)(W + (size_t)r * NN + kc + c);
            __half2 w0 = __floats2half2_rn(wv.x, wv.y);
            __half2 w1 = __floats2half2_rn(wv.z, wv.w);
            *(uint2*)&wh[r][c] = make_uint2(h2bits(w0), h2bits(w1));
        }
        __syncthreads();

#pragma unroll
        for (int k0 = 0; k0 < 64; k0 += 16) {
            // A fragment: 16x16 tile at rows [warp*16, +16), cols [k0, +16)
            unsigned a0, a1, a2, a3;
            {
                unsigned addr = (unsigned)__cvta_generic_to_shared(
                    &xh[warp * 16 + (lane & 15)][k0 + ((lane >> 4) << 3)]);
                asm volatile(
                    "ldmatrix.sync.aligned.m8n8.x4.shared.b16 {%0,%1,%2,%3}, [%4];"
                    : "=r"(a0), "=r"(a1), "=r"(a2), "=r"(a3) : "r"(addr));
            }
#pragma unroll
            for (int ot = 0; ot < 8; ot++) {
                unsigned b0, b1;
                unsigned baddr = (unsigned)__cvta_generic_to_shared(
                    &wh[ot * 8 + (lane & 7)][k0 + ((lane >> 3) & 1) * 8]);
                asm volatile(
                    "ldmatrix.sync.aligned.m8n8.x2.shared.b16 {%0,%1}, [%2];"
                    : "=r"(b0), "=r"(b1) : "r"(baddr));
                asm volatile(
                    "mma.sync.aligned.m16n8k16.row.col.f32.f16.f16.f32 "
                    "{%0,%1,%2,%3}, {%4,%5,%6,%7}, {%8,%9}, {%0,%1,%2,%3};"
                    : "+f"(acc[ot][0]), "+f"(acc[ot][1]), "+f"(acc[ot][2]), "+f"(acc[ot][3])
                    : "r"(a0), "r"(a1), "r"(a2), "r"(a3), "r"(b0), "r"(b1));
            }
        }
    }

    // epilogue: thread holds (c0,c1)@row=lane/4, (c2,c3)@row+8; cols = (lane%4)*2
    const int gid = lane >> 2;
    const int qid = lane & 3;
    const int m0 = g0 + warp * 16 + gid;
#pragma unroll
    for (int ot = 0; ot < 8; ot++) {
        int o = ot * 8 + qid * 2;
        *(float2*)(out2 + (size_t)m0 * ODIM + o) = make_float2(acc[ot][0], acc[ot][1]);
        *(float2*)(out2 + (size_t)(m0 + 8) * ODIM + o) = make_float2(acc[ot][2], acc[ot][3]);
    }
}

// ---------------------------------------------------------------------------
extern "C" void kernel_launch(void* const* d_in, const int* in_sizes, int n_in,
                              void* d_out, int out_size) {
    const float* inp = (const float*)d_in[0];  // [32,512,64]
    const float* B = (const float*)d_in[1];    // [4096,64]
    const float* W = (const float*)d_in[2];    // [64,4096]
    const float* m = (const float*)d_in[3];    // [4096,8]
    const float* n = (const float*)d_in[4];    // [4096,8]

    float* xseq = (float*)d_out;               // [32,513,4096]
    float* out2 = (float*)d_out + XSEQ_ELEMS;  // [32,512,64]

    {
        dim3 grid(NN / 64, (NTRI * TSTEPS) / 128);
        proj_kernel<<<grid, 256>>>(inp, B);
    }
    rnn_scan_kernel<<<NTRI, 512>>>(m, n, xseq);
    out_kernel<<<(NTRI * TSTEPS) / 64, 128>>>(xseq, W, out2);
}

// round 16
// speedup vs baseline: 1.0150x; 1.0007x over previous
#include <cuda_runtime.h>
#include <cuda_fp16.h>
#include <cstdint>

// Problem constants
#define NTRI 32
#define TSTEPS 512
#define IDIM 64
#define NN 4096
#define RR 8
#define ODIM 64
#define DT 0.1f

#define XSEQ_ELEMS (32ll * 513 * 4096)

// Scratch: inp_proj [b][t][j] : 32*512*4096 floats = 268 MB
__device__ float g_uproj[(size_t)NTRI * TSTEPS * NN];

__device__ __forceinline__ float sigmoid_fast(float x) {
    float t;
    asm("tanh.approx.f32 %0, %1;" : "=f"(t) : "f"(0.5f * x));
    return fmaf(0.5f, t, 0.5f);
}

__device__ __forceinline__ __half2 shfl_xor_h2(__half2 v, int m) {
    unsigned u = *reinterpret_cast<unsigned*>(&v);
    u = __shfl_xor_sync(0xffffffffu, u, m);
    return *reinterpret_cast<__half2*>(&u);
}

__device__ __forceinline__ unsigned h2bits(__half2 v) {
    return *reinterpret_cast<unsigned*>(&v);
}

// ---- packed f32x2 (Blackwell FFMA2) ----
__device__ __forceinline__ unsigned long long pack2(float lo, float hi) {
    unsigned long long r;
    asm("mov.b64 %0, {%1, %2};" : "=l"(r) : "f"(lo), "f"(hi));
    return r;
}
__device__ __forceinline__ void unpack2(unsigned long long v, float& lo, float& hi) {
    asm("mov.b64 {%0, %1}, %2;" : "=f"(lo), "=f"(hi) : "l"(v));
}
__device__ __forceinline__ unsigned long long ffma2(unsigned long long a,
                                                    unsigned long long b,
                                                    unsigned long long c) {
    unsigned long long d;
    asm("fma.rn.f32x2 %0, %1, %2, %3;" : "=l"(d) : "l"(a), "l"(b), "l"(c));
    return d;
}

// ---------------------------------------------------------------------------
// Kernel 1: inp_proj[b][t][j] = sum_i inp[b][t][i] * B[j][i]  (R9 config)
// ---------------------------------------------------------------------------
__global__ void __launch_bounds__(256) proj_kernel(const float* __restrict__ inp,
                                                   const float* __restrict__ B) {
    __shared__ __align__(16) float a_s[32][132];
    __shared__ __align__(16) float b_s[32][68];

    const int tid = threadIdx.x;
    const int g0 = blockIdx.y * 128;
    const int jb0 = blockIdx.x * 64;
    const int ty = tid >> 4;
    const int tx = tid & 15;
    const int bt0 = ty * 8;
    const int j0 = tx * 4;

    unsigned long long acc2[4][4];
#pragma unroll
    for (int i = 0; i < 4; i++)
#pragma unroll
        for (int j = 0; j < 4; j++) acc2[i][j] = 0ull;

#pragma unroll
    for (int kc = 0; kc < 2; kc++) {
        if (kc) __syncthreads();
#pragma unroll
        for (int it = 0; it < 4; it++) {
            int q = tid + it * 256;
            int r = q >> 3;
            int c4 = q & 7;
            float4 av = *(const float4*)(inp + (size_t)(g0 + r) * 64 + kc * 32 + c4 * 4);
            a_s[c4 * 4 + 0][r] = av.x;
            a_s[c4 * 4 + 1][r] = av.y;
            a_s[c4 * 4 + 2][r] = av.z;
            a_s[c4 * 4 + 3][r] = av.w;
        }
#pragma unroll
        for (int it = 0; it < 2; it++) {
            int q = tid + it * 256;
            int jr = q >> 3;
            int c4 = q & 7;
            float4 bv = *(const float4*)(B + (size_t)(jb0 + jr) * 64 + kc * 32 + c4 * 4);
            b_s[c4 * 4 + 0][jr] = bv.x;
            b_s[c4 * 4 + 1][jr] = bv.y;
            b_s[c4 * 4 + 2][jr] = bv.z;
            b_s[c4 * 4 + 3][jr] = bv.w;
        }
        __syncthreads();
#pragma unroll
        for (int k = 0; k < 32; k++) {
            ulonglong2 ap0 = *(const ulonglong2*)&a_s[k][bt0];
            ulonglong2 ap1 = *(const ulonglong2*)&a_s[k][bt0 + 4];
            unsigned long long ap[4] = {ap0.x, ap0.y, ap1.x, ap1.y};
            float4 bb = *(const float4*)&b_s[k][j0];
            unsigned long long bd[4] = {pack2(bb.x, bb.x), pack2(bb.y, bb.y),
                                        pack2(bb.z, bb.z), pack2(bb.w, bb.w)};
#pragma unroll
            for (int i = 0; i < 4; i++)
#pragma unroll
                for (int j = 0; j < 4; j++) acc2[i][j] = ffma2(ap[i], bd[j], acc2[i][j]);
        }
    }
#pragma unroll
    for (int i = 0; i < 4; i++) {
        float r0[4], r1[4];
#pragma unroll
        for (int j = 0; j < 4; j++) unpack2(acc2[i][j], r0[j], r1[j]);
        *(float4*)(g_uproj + (size_t)(g0 + bt0 + 2 * i) * NN + jb0 + j0) =
            make_float4(r0[0], r0[1], r0[2], r0[3]);
        *(float4*)(g_uproj + (size_t)(g0 + bt0 + 2 * i + 1) * NN + jb0 + j0) =
            make_float4(r1[0], r1[1], r1[2], r1[3]);
    }
}

// ---------------------------------------------------------------------------
// Kernel 2: recurrence (R9 config, proven 1024us / 4.9e-6).
// ---------------------------------------------------------------------------
__global__ void __launch_bounds__(512, 1) rnn_scan_kernel(const float* __restrict__ mg,
                                                          const float* __restrict__ ng,
                                                          float* __restrict__ xseq) {
    const int b = blockIdx.x;
    const int tid = threadIdx.x;
    const int j0 = tid * 8;
    const unsigned lane = tid & 31;
    const unsigned warp = tid >> 5;

    __shared__ __half2 part[2][4][16];

    __half2 nP[8][4];
    __half2 mPP[4][8];
#pragma unroll
    for (int k = 0; k < 8; k++) {
        const float* nr = ng + (size_t)(j0 + k) * RR;
#pragma unroll
        for (int p = 0; p < 4; p++) nP[k][p] = __floats2half2_rn(nr[2 * p], nr[2 * p + 1]);
    }
#pragma unroll
    for (int p = 0; p < 4; p++) {
        const float* m0 = mg + (size_t)(j0 + 2 * p) * RR;
        const float* m1 = mg + (size_t)(j0 + 2 * p + 1) * RR;
#pragma unroll
        for (int r = 0; r < 8; r++) mPP[p][r] = __floats2half2_rn(m0[r] * DT, m1[r] * DT);
    }

    float x[8];
    __half2 sd[8];
    const __half2 half05 = __floats2half2_rn(0.5f, 0.5f);
#pragma unroll
    for (int k = 0; k < 8; k++) {
        x[k] = 0.f;
        sd[k] = half05;
    }

    float* xrow0 = xseq + (size_t)b * 513 * NN;
    const float4 z4 = make_float4(0.f, 0.f, 0.f, 0.f);
    *(float4*)(xrow0 + j0) = z4;
    *(float4*)(xrow0 + j0 + 4) = z4;

    const float* up = g_uproj + (size_t)b * TSTEPS * NN + j0;
    const float keep = 1.0f - DT;
    const __half2 invN2 = __floats2half2_rn(1.0f / (float)NN, 1.0f / (float)NN);
    const bool hi16 = (lane & 16) != 0;
    const bool hi8 = (lane & 8) != 0;
    const bool lo16 = !hi16;

    float4 u0 = __ldg((const float4*)up);
    float4 u1 = __ldg((const float4*)(up + 4));

    for (int t = 0; t < TSTEPS; t++) {
        float4 p0, p1;
        if (t + 1 < TSTEPS) {
            p0 = __ldg((const float4*)(up + (size_t)(t + 1) * NN));
            p1 = __ldg((const float4*)(up + (size_t)(t + 1) * NN + 4));
        } else {
            p0 = z4; p1 = z4;
        }

        __half2 h[4];
#pragma unroll
        for (int p = 0; p < 4; p++) h[p] = __floats2half2_rn(0.f, 0.f);
#pragma unroll
        for (int k = 0; k < 8; k++) {
#pragma unroll
            for (int p = 0; p < 4; p++) h[p] = __hfma2(sd[k], nP[k][p], h[p]);
        }

#pragma unroll
        for (int p = 0; p < 2; p++) {
            __half2 snd = hi16 ? h[p] : h[p + 2];
            __half2 rcv = shfl_xor_h2(snd, 16);
            h[p] = __hadd2(hi16 ? h[p + 2] : h[p], rcv);
        }
        {
            __half2 snd = hi8 ? h[0] : h[1];
            __half2 rcv = shfl_xor_h2(snd, 8);
            h[0] = __hadd2(hi8 ? h[1] : h[0], rcv);
        }
        h[0] = __hadd2(h[0], shfl_xor_h2(h[0], 4));
        h[0] = __hadd2(h[0], shfl_xor_h2(h[0], 2));
        h[0] = __hadd2(h[0], shfl_xor_h2(h[0], 1));

        const int buf = t & 1;
        if ((lane & 7) == 0) {
            part[buf][lane >> 3][warp] = h[0];
        }
        __syncthreads();

        const __half2* flat = &part[buf][0][0];
        __half2 a = flat[lane];
        __half2 c = flat[lane + 32];
#pragma unroll
        for (int d = 8; d > 0; d >>= 1) {
            a = __hadd2(a, shfl_xor_h2(a, d));
            c = __hadd2(c, shfl_xor_h2(c, d));
        }
        __half2 a2 = shfl_xor_h2(a, 16);
        __half2 c2 = shfl_xor_h2(c, 16);
        __half2 vh[4];
        vh[0] = __hmul2(lo16 ? a : a2, invN2);
        vh[1] = __hmul2(lo16 ? a2 : a, invN2);
        vh[2] = __hmul2(lo16 ? c : c2, invN2);
        vh[3] = __hmul2(lo16 ? c2 : c, invN2);

        __half2 vb[8];
#pragma unroll
        for (int p = 0; p < 4; p++) {
            vb[2 * p] = __low2half2(vh[p]);
            vb[2 * p + 1] = __high2half2(vh[p]);
        }

        float ua[8] = {u0.x, u0.y, u0.z, u0.w, u1.x, u1.y, u1.z, u1.w};

#pragma unroll
        for (int p = 0; p < 4; p++) {
            __half2 rp = __hmul2(vb[0], mPP[p][0]);
#pragma unroll
            for (int r = 1; r < 8; r++) rp = __hfma2(vb[r], mPP[p][r], rp);
            float2 rf = __half22float2(rp);
            const int k0 = 2 * p, k1 = 2 * p + 1;
            x[k0] = fmaf(keep, x[k0], fmaf(DT, ua[k0], rf.x));
            x[k1] = fmaf(keep, x[k1], fmaf(DT, ua[k1], rf.y));
            float s0 = sigmoid_fast(x[k0]);
            float s1 = sigmoid_fast(x[k1]);
            sd[k0] = __half2half2(__float2half_rn(s0));
            sd[k1] = __half2half2(__float2half_rn(s1));
        }

        float* dst = xrow0 + (size_t)(t + 1) * NN + j0;
        *(float4*)dst = make_float4(x[0], x[1], x[2], x[3]);
        *(float4*)(dst + 4) = make_float4(x[4], x[5], x[6], x[7]);

        u0 = p0; u1 = p1;
    }
}

// ---------------------------------------------------------------------------
// Kernel 3: y[b][t][o] = sum_j sigmoid(x_seq[b][t+1][j]) * W[o][j]
// Tensor-core version: mma.sync.m16n8k16 fp16 inputs, fp32 accum.
// CTA: 128 thr (4 warps), tile 64bt x 64o, K chunks of 64.
// ---------------------------------------------------------------------------
__global__ void __launch_bounds__(128) out_kernel(const float* __restrict__ xseq,
                                                  const float* __restrict__ W,
                                                  float* __restrict__ out2) {
    __shared__ __align__(16) __half xh[64][72];  // [bt][k] sigmoid applied
    __shared__ __align__(16) __half wh[64][72];  // [o][k]

    const int tid = threadIdx.x;
    const int warp = tid >> 5;
    const int lane = tid & 31;
    const int g0 = blockIdx.x * 64;  // bt base (64 | 512: within one trial)
    const int bb = g0 >> 9;
    const int t0 = g0 & 511;
    const float* xbase = xseq + (size_t)bb * 513 * NN + (size_t)(t0 + 1) * NN;

    float acc[8][4];
#pragma unroll
    for (int ot = 0; ot < 8; ot++)
#pragma unroll
        for (int i = 0; i < 4; i++) acc[ot][i] = 0.f;

    for (int kc = 0; kc < NN; kc += 64) {
        if (kc) __syncthreads();
        // load x tile (sigmoid+cvt) and W tile (cvt): 64 rows x 64 k each
#pragma unroll
        for (int it = 0; it < 8; it++) {
            int idx = tid + it * 128;   // 0..1023
            int r = idx >> 4;           // row 0..63
            int c = (idx & 15) * 4;     // k col
            float4 xv = *(const float4*)(xbase + (size_t)r * NN + kc + c);
            __half2 h0 = __floats2half2_rn(sigmoid_fast(xv.x), sigmoid_fast(xv.y));
            __half2 h1 = __floats2half2_rn(sigmoid_fast(xv.z), sigmoid_fast(xv.w));
            *(uint2*)&xh[r][c] = make_uint2(h2bits(h0), h2bits(h1));
            float4 wv = *(const float4*)(W + (size_t)r * NN + kc + c);
            __half2 w0 = __floats2half2_rn(wv.x, wv.y);
            __half2 w1 = __floats2half2_rn(wv.z, wv.w);
            *(uint2*)&wh[r][c] = make_uint2(h2bits(w0), h2bits(w1));
        }
        __syncthreads();

#pragma unroll
        for (int k0 = 0; k0 < 64; k0 += 16) {
            // A fragment: 16x16 tile at rows [warp*16, +16), cols [k0, +16)
            unsigned a0, a1, a2, a3;
            {
                unsigned addr = (unsigned)__cvta_generic_to_shared(
                    &xh[warp * 16 + (lane & 15)][k0 + ((lane >> 4) << 3)]);
                asm volatile(
                    "ldmatrix.sync.aligned.m8n8.x4.shared.b16 {%0,%1,%2,%3}, [%4];"
                    : "=r"(a0), "=r"(a1), "=r"(a2), "=r"(a3) : "r"(addr));
            }
#pragma unroll
            for (int ot = 0; ot < 8; ot++) {
                unsigned b0, b1;
                unsigned baddr = (unsigned)__cvta_generic_to_shared(
                    &wh[ot * 8 + (lane & 7)][k0 + ((lane >> 3) & 1) * 8]);
                asm volatile(
                    "ldmatrix.sync.aligned.m8n8.x2.shared.b16 {%0,%1}, [%2];"
                    : "=r"(b0), "=r"(b1) : "r"(baddr));
                asm volatile(
                    "mma.sync.aligned.m16n8k16.row.col.f32.f16.f16.f32 "
                    "{%0,%1,%2,%3}, {%4,%5,%6,%7}, {%8,%9}, {%0,%1,%2,%3};"
                    : "+f"(acc[ot][0]), "+f"(acc[ot][1]), "+f"(acc[ot][2]), "+f"(acc[ot][3])
                    : "r"(a0), "r"(a1), "r"(a2), "r"(a3), "r"(b0), "r"(b1));
            }
        }
    }

    // epilogue: thread holds (c0,c1)@row=lane/4, (c2,c3)@row+8; cols = (lane%4)*2
    const int gid = lane >> 2;
    const int qid = lane & 3;
    const int m0 = g0 + warp * 16 + gid;
#pragma unroll
    for (int ot = 0; ot < 8; ot++) {
        int o = ot * 8 + qid * 2;
        *(float2*)(out2 + (size_t)m0 * ODIM + o) = make_float2(acc[ot][0], acc[ot][1]);
        *(float2*)(out2 + (size_t)(m0 + 8) * ODIM + o) = make_float2(acc[ot][2], acc[ot][3]);
    }
}

// ---------------------------------------------------------------------------
extern "C" void kernel_launch(void* const* d_in, const int* in_sizes, int n_in,
                              void* d_out, int out_size) {
    const float* inp = (const float*)d_in[0];  // [32,512,64]
    const float* B = (const float*)d_in[1];    // [4096,64]
    const float* W = (const float*)d_in[2];    // [64,4096]
    const float* m = (const float*)d_in[3];    // [4096,8]
    const float* n = (const float*)d_in[4];    // [4096,8]

    float* xseq = (float*)d_out;               // [32,513,4096]
    float* out2 = (float*)d_out + XSEQ_ELEMS;  // [32,512,64]

    {
        dim3 grid(NN / 64, (NTRI * TSTEPS) / 128);
        proj_kernel<<<grid, 256>>>(inp, B);
    }
    rnn_scan_kernel<<<NTRI, 512>>>(m, n, xseq);
    out_kernel<<<(NTRI * TSTEPS) / 64, 128>>>(xseq, W, out2);
}

// round 17
// speedup vs baseline: 1.1517x; 1.1347x over previous
#include <cuda_runtime.h>
#include <cuda_fp16.h>
#include <cstdint>

// Problem constants
#define NTRI 32
#define TSTEPS 512
#define IDIM 64
#define NN 4096
#define RR 8
#define ODIM 64
#define DT 0.1f

#define XSEQ_ELEMS (32ll * 513 * 4096)

// Scratch: inp_proj [b][t][j] : 32*512*4096 floats = 268 MB
__device__ float g_uproj[(size_t)NTRI * TSTEPS * NN];

__device__ __forceinline__ float sigmoid_fast(float x) {
    float t;
    asm("tanh.approx.f32 %0, %1;" : "=f"(t) : "f"(0.5f * x));
    return fmaf(0.5f, t, 0.5f);
}

__device__ __forceinline__ __half2 shfl_xor_h2(__half2 v, int m) {
    unsigned u = *reinterpret_cast<unsigned*>(&v);
    u = __shfl_xor_sync(0xffffffffu, u, m);
    return *reinterpret_cast<__half2*>(&u);
}

__device__ __forceinline__ unsigned h2bits(__half2 v) {
    return *reinterpret_cast<unsigned*>(&v);
}

// ---------------------------------------------------------------------------
// Kernel 1: inp_proj[b][t][j] = sum_i inp[b][t][i] * B[j][i]
// Tensor-core version: mma.sync.m16n8k16 fp16 inputs, fp32 accum.
// CTA: 128 thr (4 warps), tile 64bt x 128j, K=64 loaded once.
// ---------------------------------------------------------------------------
__global__ void __launch_bounds__(128) proj_kernel(const float* __restrict__ inp,
                                                   const float* __restrict__ B) {
    __shared__ __align__(16) __half ah[64][72];   // [bt][k]
    __shared__ __align__(16) __half bh[128][72];  // [j][k]

    const int tid = threadIdx.x;
    const int warp = tid >> 5;
    const int lane = tid & 31;
    const int g0 = blockIdx.y * 64;    // bt base
    const int jb0 = blockIdx.x * 128;  // j base

    // load inp tile: 64 bt rows x 64 k, fp32 -> fp16
#pragma unroll
    for (int it = 0; it < 8; it++) {
        int idx = tid + it * 128;  // 0..1023
        int r = idx >> 4;          // 0..63
        int c = (idx & 15) * 4;    // k col
        float4 v = *(const float4*)(inp + (size_t)(g0 + r) * 64 + c);
        __half2 h0 = __floats2half2_rn(v.x, v.y);
        __half2 h1 = __floats2half2_rn(v.z, v.w);
        *(uint2*)&ah[r][c] = make_uint2(h2bits(h0), h2bits(h1));
    }
    // load B tile: 128 j rows x 64 k, fp32 -> fp16
#pragma unroll
    for (int it = 0; it < 16; it++) {
        int idx = tid + it * 128;  // 0..2047
        int r = idx >> 4;          // 0..127
        int c = (idx & 15) * 4;
        float4 v = *(const float4*)(B + (size_t)(jb0 + r) * 64 + c);
        __half2 h0 = __floats2half2_rn(v.x, v.y);
        __half2 h1 = __floats2half2_rn(v.z, v.w);
        *(uint2*)&bh[r][c] = make_uint2(h2bits(h0), h2bits(h1));
    }
    __syncthreads();

    float acc[16][4];
#pragma unroll
    for (int ot = 0; ot < 16; ot++)
#pragma unroll
        for (int i = 0; i < 4; i++) acc[ot][i] = 0.f;

#pragma unroll
    for (int k0 = 0; k0 < 64; k0 += 16) {
        // A fragment: 16x16 tile at rows [warp*16, +16), cols [k0, +16)
        unsigned a0, a1, a2, a3;
        {
            unsigned addr = (unsigned)__cvta_generic_to_shared(
                &ah[warp * 16 + (lane & 15)][k0 + ((lane >> 4) << 3)]);
            asm volatile(
                "ldmatrix.sync.aligned.m8n8.x4.shared.b16 {%0,%1,%2,%3}, [%4];"
                : "=r"(a0), "=r"(a1), "=r"(a2), "=r"(a3) : "r"(addr));
        }
#pragma unroll
        for (int ot = 0; ot < 16; ot++) {
            unsigned b0, b1;
            unsigned baddr = (unsigned)__cvta_generic_to_shared(
                &bh[ot * 8 + (lane & 7)][k0 + ((lane >> 3) & 1) * 8]);
            asm volatile(
                "ldmatrix.sync.aligned.m8n8.x2.shared.b16 {%0,%1}, [%2];"
                : "=r"(b0), "=r"(b1) : "r"(baddr));
            asm volatile(
                "mma.sync.aligned.m16n8k16.row.col.f32.f16.f16.f32 "
                "{%0,%1,%2,%3}, {%4,%5,%6,%7}, {%8,%9}, {%0,%1,%2,%3};"
                : "+f"(acc[ot][0]), "+f"(acc[ot][1]), "+f"(acc[ot][2]), "+f"(acc[ot][3])
                : "r"(a0), "r"(a1), "r"(a2), "r"(a3), "r"(b0), "r"(b1));
        }
    }

    // epilogue: thread holds (c0,c1)@row=lane/4, (c2,c3)@row+8; cols=(lane%4)*2
    const int gid = lane >> 2;
    const int qid = lane & 3;
    const int m0 = g0 + warp * 16 + gid;
#pragma unroll
    for (int ot = 0; ot < 16; ot++) {
        int j = jb0 + ot * 8 + qid * 2;
        *(float2*)(g_uproj + (size_t)m0 * NN + j) = make_float2(acc[ot][0], acc[ot][1]);
        *(float2*)(g_uproj + (size_t)(m0 + 8) * NN + j) = make_float2(acc[ot][2], acc[ot][3]);
    }
}

// ---------------------------------------------------------------------------
// Kernel 2: recurrence (R9 config, proven).
// ---------------------------------------------------------------------------
__global__ void __launch_bounds__(512, 1) rnn_scan_kernel(const float* __restrict__ mg,
                                                          const float* __restrict__ ng,
                                                          float* __restrict__ xseq) {
    const int b = blockIdx.x;
    const int tid = threadIdx.x;
    const int j0 = tid * 8;
    const unsigned lane = tid & 31;
    const unsigned warp = tid >> 5;

    __shared__ __half2 part[2][4][16];

    __half2 nP[8][4];
    __half2 mPP[4][8];
#pragma unroll
    for (int k = 0; k < 8; k++) {
        const float* nr = ng + (size_t)(j0 + k) * RR;
#pragma unroll
        for (int p = 0; p < 4; p++) nP[k][p] = __floats2half2_rn(nr[2 * p], nr[2 * p + 1]);
    }
#pragma unroll
    for (int p = 0; p < 4; p++) {
        const float* m0 = mg + (size_t)(j0 + 2 * p) * RR;
        const float* m1 = mg + (size_t)(j0 + 2 * p + 1) * RR;
#pragma unroll
        for (int r = 0; r < 8; r++) mPP[p][r] = __floats2half2_rn(m0[r] * DT, m1[r] * DT);
    }

    float x[8];
    __half2 sd[8];
    const __half2 half05 = __floats2half2_rn(0.5f, 0.5f);
#pragma unroll
    for (int k = 0; k < 8; k++) {
        x[k] = 0.f;
        sd[k] = half05;
    }

    float* xrow0 = xseq + (size_t)b * 513 * NN;
    const float4 z4 = make_float4(0.f, 0.f, 0.f, 0.f);
    *(float4*)(xrow0 + j0) = z4;
    *(float4*)(xrow0 + j0 + 4) = z4;

    const float* up = g_uproj + (size_t)b * TSTEPS * NN + j0;
    const float keep = 1.0f - DT;
    const __half2 invN2 = __floats2half2_rn(1.0f / (float)NN, 1.0f / (float)NN);
    const bool hi16 = (lane & 16) != 0;
    const bool hi8 = (lane & 8) != 0;
    const bool lo16 = !hi16;

    float4 u0 = __ldg((const float4*)up);
    float4 u1 = __ldg((const float4*)(up + 4));

    for (int t = 0; t < TSTEPS; t++) {
        float4 p0, p1;
        if (t + 1 < TSTEPS) {
            p0 = __ldg((const float4*)(up + (size_t)(t + 1) * NN));
            p1 = __ldg((const float4*)(up + (size_t)(t + 1) * NN + 4));
        } else {
            p0 = z4; p1 = z4;
        }

        __half2 h[4];
#pragma unroll
        for (int p = 0; p < 4; p++) h[p] = __floats2half2_rn(0.f, 0.f);
#pragma unroll
        for (int k = 0; k < 8; k++) {
#pragma unroll
            for (int p = 0; p < 4; p++) h[p] = __hfma2(sd[k], nP[k][p], h[p]);
        }

#pragma unroll
        for (int p = 0; p < 2; p++) {
            __half2 snd = hi16 ? h[p] : h[p + 2];
            __half2 rcv = shfl_xor_h2(snd, 16);
            h[p] = __hadd2(hi16 ? h[p + 2] : h[p], rcv);
        }
        {
            __half2 snd = hi8 ? h[0] : h[1];
            __half2 rcv = shfl_xor_h2(snd, 8);
            h[0] = __hadd2(hi8 ? h[1] : h[0], rcv);
        }
        h[0] = __hadd2(h[0], shfl_xor_h2(h[0], 4));
        h[0] = __hadd2(h[0], shfl_xor_h2(h[0], 2));
        h[0] = __hadd2(h[0], shfl_xor_h2(h[0], 1));

        const int buf = t & 1;
        if ((lane & 7) == 0) {
            part[buf][lane >> 3][warp] = h[0];
        }
        __syncthreads();

        const __half2* flat = &part[buf][0][0];
        __half2 a = flat[lane];
        __half2 c = flat[lane + 32];
#pragma unroll
        for (int d = 8; d > 0; d >>= 1) {
            a = __hadd2(a, shfl_xor_h2(a, d));
            c = __hadd2(c, shfl_xor_h2(c, d));
        }
        __half2 a2 = shfl_xor_h2(a, 16);
        __half2 c2 = shfl_xor_h2(c, 16);
        __half2 vh[4];
        vh[0] = __hmul2(lo16 ? a : a2, invN2);
        vh[1] = __hmul2(lo16 ? a2 : a, invN2);
        vh[2] = __hmul2(lo16 ? c : c2, invN2);
        vh[3] = __hmul2(lo16 ? c2 : c, invN2);

        __half2 vb[8];
#pragma unroll
        for (int p = 0; p < 4; p++) {
            vb[2 * p] = __low2half2(vh[p]);
            vb[2 * p + 1] = __high2half2(vh[p]);
        }

        float ua[8] = {u0.x, u0.y, u0.z, u0.w, u1.x, u1.y, u1.z, u1.w};

#pragma unroll
        for (int p = 0; p < 4; p++) {
            __half2 rp = __hmul2(vb[0], mPP[p][0]);
#pragma unroll
            for (int r = 1; r < 8; r++) rp = __hfma2(vb[r], mPP[p][r], rp);
            float2 rf = __half22float2(rp);
            const int k0 = 2 * p, k1 = 2 * p + 1;
            x[k0] = fmaf(keep, x[k0], fmaf(DT, ua[k0], rf.x));
            x[k1] = fmaf(keep, x[k1], fmaf(DT, ua[k1], rf.y));
            float s0 = sigmoid_fast(x[k0]);
            float s1 = sigmoid_fast(x[k1]);
            sd[k0] = __half2half2(__float2half_rn(s0));
            sd[k1] = __half2half2(__float2half_rn(s1));
        }

        float* dst = xrow0 + (size_t)(t + 1) * NN + j0;
        *(float4*)dst = make_float4(x[0], x[1], x[2], x[3]);
        *(float4*)(dst + 4) = make_float4(x[4], x[5], x[6], x[7]);

        u0 = p0; u1 = p1;
    }
}

// ---------------------------------------------------------------------------
// Kernel 3: y[b][t][o] = sum_j sigmoid(x_seq[b][t+1][j]) * W[o][j]
// Tensor-core version (R16, proven). CTA: 128 thr, tile 64bt x 64o.
// ---------------------------------------------------------------------------
__global__ void __launch_bounds__(128) out_kernel(const float* __restrict__ xseq,
                                                  const float* __restrict__ W,
                                                  float* __restrict__ out2) {
    __shared__ __align__(16) __half xh[64][72];
    __shared__ __align__(16) __half wh[64][72];

    const int tid = threadIdx.x;
    const int warp = tid >> 5;
    const int lane = tid & 31;
    const int g0 = blockIdx.x * 64;
    const int bb = g0 >> 9;
    const int t0 = g0 & 511;
    const float* xbase = xseq + (size_t)bb * 513 * NN + (size_t)(t0 + 1) * NN;

    float acc[8][4];
#pragma unroll
    for (int ot = 0; ot < 8; ot++)
#pragma unroll
        for (int i = 0; i < 4; i++) acc[ot][i] = 0.f;

    for (int kc = 0; kc < NN; kc += 64) {
        if (kc) __syncthreads();
#pragma unroll
        for (int it = 0; it < 8; it++) {
            int idx = tid + it * 128;
            int r = idx >> 4;
            int c = (idx & 15) * 4;
            float4 xv = *(const float4*)(xbase + (size_t)r * NN + kc + c);
            __half2 h0 = __floats2half2_rn(sigmoid_fast(xv.x), sigmoid_fast(xv.y));
            __half2 h1 = __floats2half2_rn(sigmoid_fast(xv.z), sigmoid_fast(xv.w));
            *(uint2*)&xh[r][c] = make_uint2(h2bits(h0), h2bits(h1));
            float4 wv = *(const float4*)(W + (size_t)r * NN + kc + c);
            __half2 w0 = __floats2half2_rn(wv.x, wv.y);
            __half2 w1 = __floats2half2_rn(wv.z, wv.w);
            *(uint2*)&wh[r][c] = make_uint2(h2bits(w0), h2bits(w1));
        }
        __syncthreads();

#pragma unroll
        for (int k0 = 0; k0 < 64; k0 += 16) {
            unsigned a0, a1, a2, a3;
            {
                unsigned addr = (unsigned)__cvta_generic_to_shared(
                    &xh[warp * 16 + (lane & 15)][k0 + ((lane >> 4) << 3)]);
                asm volatile(
                    "ldmatrix.sync.aligned.m8n8.x4.shared.b16 {%0,%1,%2,%3}, [%4];"
                    : "=r"(a0), "=r"(a1), "=r"(a2), "=r"(a3) : "r"(addr));
            }
#pragma unroll
            for (int ot = 0; ot < 8; ot++) {
                unsigned b0, b1;
                unsigned baddr = (unsigned)__cvta_generic_to_shared(
                    &wh[ot * 8 + (lane & 7)][k0 + ((lane >> 3) & 1) * 8]);
                asm volatile(
                    "ldmatrix.sync.aligned.m8n8.x2.shared.b16 {%0,%1}, [%2];"
                    : "=r"(b0), "=r"(b1) : "r"(baddr));
                asm volatile(
                    "mma.sync.aligned.m16n8k16.row.col.f32.f16.f16.f32 "
                    "{%0,%1,%2,%3}, {%4,%5,%6,%7}, {%8,%9}, {%0,%1,%2,%3};"
                    : "+f"(acc[ot][0]), "+f"(acc[ot][1]), "+f"(acc[ot][2]), "+f"(acc[ot][3])
                    : "r"(a0), "r"(a1), "r"(a2), "r"(a3), "r"(b0), "r"(b1));
            }
        }
    }

    const int gid = lane >> 2;
    const int qid = lane & 3;
    const int m0 = g0 + warp * 16 + gid;
#pragma unroll
    for (int ot = 0; ot < 8; ot++) {
        int o = ot * 8 + qid * 2;
        *(float2*)(out2 + (size_t)m0 * ODIM + o) = make_float2(acc[ot][0], acc[ot][1]);
        *(float2*)(out2 + (size_t)(m0 + 8) * ODIM + o) = make_float2(acc[ot][2], acc[ot][3]);
    }
}

// ---------------------------------------------------------------------------
extern "C" void kernel_launch(void* const* d_in, const int* in_sizes, int n_in,
                              void* d_out, int out_size) {
    const float* inp = (const float*)d_in[0];  // [32,512,64]
    const float* B = (const float*)d_in[1];    // [4096,64]
    const float* W = (const float*)d_in[2];    // [64,4096]
    const float* m = (const float*)d_in[3];    // [4096,8]
    const float* n = (const float*)d_in[4];    // [4096,8]

    float* xseq = (float*)d_out;               // [32,513,4096]
    float* out2 = (float*)d_out + XSEQ_ELEMS;  // [32,512,64]

    {
        dim3 grid(NN / 128, (NTRI * TSTEPS) / 64);
        proj_kernel<<<grid, 128>>>(inp, B);
    }
    rnn_scan_kernel<<<NTRI, 512>>>(m, n, xseq);
    out_kernel<<<(NTRI * TSTEPS) / 64, 128>>>(xseq, W, out2);
}